// round 1
// baseline (speedup 1.0000x reference)
#include <cuda_runtime.h>

#define NN 100000
#define EE 1600000
#define DD 64

// ---- persistent scratch (device globals; no runtime allocation) ----
__device__ int   g_cnt[NN];        // in-degree histogram (edges only)
__device__ int   g_fill[NN];       // CSR fill cursors
__device__ int   g_rowptr[NN + 1]; // CSR row pointers (by dst)
__device__ float g_dis[NN];        // deg^{-1/2} (deg includes self-loop)
__device__ int   g_col[EE];        // CSR column = src node
__device__ float g_wgt[EE];        // precomputed dis[src]*dis[dst]
__device__ float g_h[(size_t)NN * DD];   // per-layer GEMM output
__device__ float g_x[(size_t)NN * DD];   // layer activation ping buffer

// ---------------------------------------------------------------------------
__global__ void init_k(int n) {
    int i = blockIdx.x * blockDim.x + threadIdx.x;
    if (i < n) { g_cnt[i] = 0; g_fill[i] = 0; }
}

__global__ void hist_k(const int* __restrict__ dst, int e) {
    int i = blockIdx.x * blockDim.x + threadIdx.x;
    if (i < e) atomicAdd(&g_cnt[dst[i]], 1);
}

// Single-block inclusive scan over g_cnt -> g_rowptr, plus dis = rsqrt(deg+1).
// 1024 threads, ~98 sequential chunks. Cheap (~10-20us), runs once.
__global__ void scan_k(int n) {
    __shared__ int wsum[32];
    __shared__ int carry_s;
    const int tid = threadIdx.x, lane = tid & 31, wid = tid >> 5;
    int carry = 0;
    if (tid == 0) g_rowptr[0] = 0;
    for (int base = 0; base < n; base += 1024) {
        int i = base + tid;
        int v = (i < n) ? g_cnt[i] : 0;
        if (i < n) g_dis[i] = rsqrtf((float)(v + 1)); // +1 self-loop
        int x = v;
        #pragma unroll
        for (int o = 1; o < 32; o <<= 1) {
            int y = __shfl_up_sync(0xffffffffu, x, o);
            if (lane >= o) x += y;
        }
        if (lane == 31) wsum[wid] = x;
        __syncthreads();
        if (wid == 0) {
            int s = wsum[lane], t = s;
            #pragma unroll
            for (int o = 1; o < 32; o <<= 1) {
                int y = __shfl_up_sync(0xffffffffu, t, o);
                if (lane >= o) t += y;
            }
            wsum[lane] = t - s; // exclusive prefix of warp sums
        }
        __syncthreads();
        int incl = x + wsum[wid] + carry;
        if (i < n) g_rowptr[i + 1] = incl;
        if (tid == 1023) carry_s = incl;
        __syncthreads();
        carry = carry_s;
    }
}

__global__ void scat_k(const int* __restrict__ src, const int* __restrict__ dst, int e) {
    int i = blockIdx.x * blockDim.x + threadIdx.x;
    if (i < e) {
        int s = src[i], d = dst[i];
        int pos = g_rowptr[d] + atomicAdd(&g_fill[d], 1);
        g_col[pos] = s;
        g_wgt[pos] = g_dis[s] * g_dis[d];
    }
}

// ---------------------------------------------------------------------------
// H = X @ W.  Warp per row; W staged in smem; x row in registers, broadcast
// via shfl. Each lane produces output cols {2*lane, 2*lane+1} (conflict-free
// LDS.64 on W rows, coalesced 256B float2 store).
__global__ void gemm_k(const float* __restrict__ Xext, int use_ext,
                       const float* __restrict__ W, int n) {
    __shared__ float Ws[DD * DD];
    for (int i = threadIdx.x; i < DD * DD; i += blockDim.x) Ws[i] = W[i];
    __syncthreads();

    const float* X = use_ext ? Xext : g_x;
    const int lane = threadIdx.x & 31;
    const int warp = threadIdx.x >> 5;
    const int wpb  = blockDim.x >> 5;

    for (int row = blockIdx.x * wpb + warp; row < n; row += gridDim.x * wpb) {
        float2 xv = reinterpret_cast<const float2*>(X + (size_t)row * DD)[lane];
        float a0 = 0.f, a1 = 0.f;
        #pragma unroll
        for (int k = 0; k < DD; k++) {
            float xk = __shfl_sync(0xffffffffu, (k & 1) ? xv.y : xv.x, k >> 1);
            float2 wv = reinterpret_cast<const float2*>(Ws + k * DD)[lane];
            a0 += xk * wv.x;
            a1 += xk * wv.y;
        }
        float2 o; o.x = a0; o.y = a1;
        reinterpret_cast<float2*>(const_cast<float*>(g_h) + (size_t)row * DD)[lane] = o;
    }
}

// ---------------------------------------------------------------------------
// out[n] = dis[n]^2 * h[n] + sum_{e: dst=n} wgt[e] * h[col[e]] + b
// One warp per node; each lane owns a float2 (cols 2l, 2l+1). Gathers are
// full 256B rows (2 x 128B lines), L2-resident since g_h = 25.6MB << L2.
__global__ void agg_k(const float* __restrict__ b, float* __restrict__ dout,
                      int use_dout, int n) {
    int gw = (blockIdx.x * blockDim.x + threadIdx.x) >> 5;
    int lane = threadIdx.x & 31;
    if (gw >= n) return;

    const int node = gw;
    const float dn = g_dis[node];
    float2 hv = reinterpret_cast<const float2*>(g_h + (size_t)node * DD)[lane];
    const float sw = dn * dn;
    float ax = sw * hv.x, ay = sw * hv.y;

    int j   = g_rowptr[node];
    int end = g_rowptr[node + 1];
    for (; j < end; j++) {
        int   s = g_col[j];
        float w = g_wgt[j];
        float2 v = reinterpret_cast<const float2*>(g_h + (size_t)s * DD)[lane];
        ax += w * v.x;
        ay += w * v.y;
    }
    float2 bv = reinterpret_cast<const float2*>(b)[lane];
    float2 o; o.x = ax + bv.x; o.y = ay + bv.y;

    float* out = use_dout ? dout : g_x;
    reinterpret_cast<float2*>(out + (size_t)node * DD)[lane] = o;
}

// ---------------------------------------------------------------------------
extern "C" void kernel_launch(void* const* d_in, const int* in_sizes, int n_in,
                              void* d_out, int out_size) {
    const float* x  = (const float*)d_in[0];
    const int*   ei = (const int*)d_in[1];
    const float* W[3] = { (const float*)d_in[2], (const float*)d_in[4], (const float*)d_in[6] };
    const float* B[3] = { (const float*)d_in[3], (const float*)d_in[5], (const float*)d_in[7] };

    int n = in_sizes[0] / DD; if (n > NN) n = NN;
    int e = in_sizes[1] / 2;  if (e > EE) e = EE;
    const int* src = ei;
    const int* dst = ei + e;

    // --- build normalized CSR once (graph is fixed across layers) ---
    init_k<<<(n + 255) / 256, 256>>>(n);
    hist_k<<<(e + 255) / 256, 256>>>(dst, e);
    scan_k<<<1, 1024>>>(n);
    scat_k<<<(e + 255) / 256, 256>>>(src, dst, e);

    const int agg_grid  = (n * 32 + 255) / 256; // one warp per node
    const int gemm_grid = 1024;                 // grid-stride, W loaded ~1k times

    // --- layer 0: input from d_in[0], output to g_x ---
    gemm_k<<<gemm_grid, 256>>>(x, 1, W[0], n);
    agg_k<<<agg_grid, 256>>>(B[0], (float*)d_out, 0, n);

    // --- layer 1: g_x -> g_x ---
    gemm_k<<<gemm_grid, 256>>>(nullptr, 0, W[1], n);
    agg_k<<<agg_grid, 256>>>(B[1], (float*)d_out, 0, n);

    // --- layer 2: g_x -> d_out ---
    gemm_k<<<gemm_grid, 256>>>(nullptr, 0, W[2], n);
    agg_k<<<agg_grid, 256>>>(B[2], (float*)d_out, 1, n);
}

// round 2
// speedup vs baseline: 1.1456x; 1.1456x over previous
#include <cuda_runtime.h>

#define NN 100000
#define EE 1600000
#define DD 64

struct __align__(8) Edge { int s; float w; };

// ---- persistent scratch (device globals; no runtime allocation) ----
__device__ int   g_cnt[NN];          // in-degree histogram (edges only)
__device__ int   g_rowptr[NN + 1];   // CSR row pointers (by dst)
__device__ int   g_cursor[NN];       // scatter cursors (init = rowptr)
__device__ float g_dis[NN];          // deg^{-1/2} (deg includes self-loop)
__device__ Edge  g_edge[EE];         // (src, dis[src]*dis[dst]) interleaved
__device__ int   g_bsum[128];        // block sums for 3-phase scan
__device__ float g_x[(size_t)NN * DD];   // activation ping
__device__ float g_y[(size_t)NN * DD];   // activation pong

// ---------------------------------------------------------------------------
__global__ void init_k(int n) {
    int i = blockIdx.x * blockDim.x + threadIdx.x;
    if (i < n) g_cnt[i] = 0;
}

__global__ void hist_k(const int* __restrict__ dst, int e) {
    int i = blockIdx.x * blockDim.x + threadIdx.x;
    if (i < e) atomicAdd(&g_cnt[dst[i]], 1);
}

// Phase 1: per-block (1024) inclusive scan of g_cnt -> g_rowptr[i+1] (local),
// block total -> g_bsum. Also dis = rsqrt(deg+1) for self-loop-added degree.
__global__ void scan1_k(int n) {
    __shared__ int wsum[32];
    const int tid = threadIdx.x, lane = tid & 31, wid = tid >> 5;
    int i = blockIdx.x * 1024 + tid;
    int v = (i < n) ? g_cnt[i] : 0;
    if (i < n) g_dis[i] = rsqrtf((float)(v + 1));
    int x = v;
    #pragma unroll
    for (int o = 1; o < 32; o <<= 1) {
        int y = __shfl_up_sync(0xffffffffu, x, o);
        if (lane >= o) x += y;
    }
    if (lane == 31) wsum[wid] = x;
    __syncthreads();
    if (wid == 0) {
        int s = wsum[lane], t = s;
        #pragma unroll
        for (int o = 1; o < 32; o <<= 1) {
            int y = __shfl_up_sync(0xffffffffu, t, o);
            if (lane >= o) t += y;
        }
        wsum[lane] = t - s;
    }
    __syncthreads();
    int incl = x + wsum[wid];
    if (i < n) g_rowptr[i + 1] = incl;
    if (tid == 1023) g_bsum[blockIdx.x] = incl;
}

// Phase 2: exclusive scan of <=128 block sums.
__global__ void scan2_k(int nb) {
    __shared__ int wsum[4];
    const int tid = threadIdx.x, lane = tid & 31, wid = tid >> 5;
    int v = (tid < nb) ? g_bsum[tid] : 0;
    int x = v;
    #pragma unroll
    for (int o = 1; o < 32; o <<= 1) {
        int y = __shfl_up_sync(0xffffffffu, x, o);
        if (lane >= o) x += y;
    }
    if (lane == 31) wsum[wid] = x;
    __syncthreads();
    int off = 0;
    #pragma unroll
    for (int w = 0; w < 4; w++) if (w < wid) off += wsum[w];
    if (tid < nb) g_bsum[tid] = x - v + off;
}

// Phase 3: finalize rowptr and materialize scatter cursors (= rowptr).
__global__ void scan3_k(int n) {
    int i = blockIdx.x * blockDim.x + threadIdx.x;
    if (i == 0) { g_rowptr[0] = 0; g_cursor[0] = 0; }
    if (i < n) {
        int fin = g_rowptr[i + 1] + g_bsum[i >> 10];
        g_rowptr[i + 1] = fin;
        if (i + 1 < n) g_cursor[i + 1] = fin;
    }
}

__global__ void scat_k(const int* __restrict__ src, const int* __restrict__ dst, int e) {
    int i = blockIdx.x * blockDim.x + threadIdx.x;
    if (i < e) {
        int s = src[i], d = dst[i];
        int pos = atomicAdd(&g_cursor[d], 1);
        Edge ed; ed.s = s; ed.w = g_dis[s] * g_dis[d];
        g_edge[pos] = ed;  // single ST.64: one random line per edge
    }
}

// ---------------------------------------------------------------------------
// Fused GCN layer via linearity reorder:
//   out[n,:] = (dis[n]^2 * X[n,:] + sum_e w[e]*X[src[e],:]) @ W + b
// One warp per node; lane owns output cols {2l, 2l+1}. Gathers are
// L2-resident (X = 25.6MB << 126MB L2). Mini-GEMM via shfl broadcast
// against smem-resident W.
__global__ void fused_k(const float* __restrict__ Xext, int src_sel,
                        const float* __restrict__ W, const float* __restrict__ bias,
                        float* __restrict__ dout, int dst_sel, int n) {
    __shared__ float Ws[DD * DD];
    for (int i = threadIdx.x; i < DD * DD; i += blockDim.x) Ws[i] = W[i];
    __syncthreads();

    const float* X = (src_sel == 0) ? Xext : (src_sel == 1 ? g_x : g_y);
    float* out     = (dst_sel == 1) ? g_x : (dst_sel == 2 ? g_y : dout);

    const int lane = threadIdx.x & 31;
    const int node = (blockIdx.x * blockDim.x + threadIdx.x) >> 5;
    if (node >= n) return;

    // ---- aggregate (A_hat @ X row) ----
    const float dn = g_dis[node];
    float2 hv = reinterpret_cast<const float2*>(X + (size_t)node * DD)[lane];
    const float sw = dn * dn;
    float ax = sw * hv.x, ay = sw * hv.y;

    int j   = g_rowptr[node];
    int end = g_rowptr[node + 1];
    for (; j + 4 <= end; j += 4) {           // batch gathers for MLP
        Edge e0 = g_edge[j + 0];
        Edge e1 = g_edge[j + 1];
        Edge e2 = g_edge[j + 2];
        Edge e3 = g_edge[j + 3];
        float2 v0 = reinterpret_cast<const float2*>(X + (size_t)e0.s * DD)[lane];
        float2 v1 = reinterpret_cast<const float2*>(X + (size_t)e1.s * DD)[lane];
        float2 v2 = reinterpret_cast<const float2*>(X + (size_t)e2.s * DD)[lane];
        float2 v3 = reinterpret_cast<const float2*>(X + (size_t)e3.s * DD)[lane];
        ax += e0.w * v0.x; ay += e0.w * v0.y;
        ax += e1.w * v1.x; ay += e1.w * v1.y;
        ax += e2.w * v2.x; ay += e2.w * v2.y;
        ax += e3.w * v3.x; ay += e3.w * v3.y;
    }
    for (; j < end; j++) {
        Edge e = g_edge[j];
        float2 v = reinterpret_cast<const float2*>(X + (size_t)e.s * DD)[lane];
        ax += e.w * v.x; ay += e.w * v.y;
    }

    // ---- mini-GEMM: y = agg @ W + b ----
    float a0 = 0.f, a1 = 0.f;
    #pragma unroll
    for (int k = 0; k < DD; k++) {
        float xk = __shfl_sync(0xffffffffu, (k & 1) ? ay : ax, k >> 1);
        float2 wv = reinterpret_cast<const float2*>(Ws + k * DD)[lane];
        a0 += xk * wv.x;
        a1 += xk * wv.y;
    }
    float2 bv = reinterpret_cast<const float2*>(bias)[lane];
    float2 o; o.x = a0 + bv.x; o.y = a1 + bv.y;
    reinterpret_cast<float2*>(out + (size_t)node * DD)[lane] = o;
}

// ---------------------------------------------------------------------------
extern "C" void kernel_launch(void* const* d_in, const int* in_sizes, int n_in,
                              void* d_out, int out_size) {
    const float* x  = (const float*)d_in[0];
    const int*   ei = (const int*)d_in[1];
    const float* W[3] = { (const float*)d_in[2], (const float*)d_in[4], (const float*)d_in[6] };
    const float* B[3] = { (const float*)d_in[3], (const float*)d_in[5], (const float*)d_in[7] };

    int n = in_sizes[0] / DD; if (n > NN) n = NN;
    int e = in_sizes[1] / 2;  if (e > EE) e = EE;
    const int* src = ei;
    const int* dst = ei + e;

    // --- build normalized CSR (rebuilt every call; graph fixed across layers) ---
    init_k<<<(n + 255) / 256, 256>>>(n);
    hist_k<<<(e + 255) / 256, 256>>>(dst, e);
    int nb = (n + 1023) / 1024;
    scan1_k<<<nb, 1024>>>(n);
    scan2_k<<<1, 128>>>(nb);
    scan3_k<<<(n + 255) / 256, 256>>>(n);
    scat_k<<<(e + 255) / 256, 256>>>(src, dst, e);

    const int grid = (n * 32 + 255) / 256; // one warp per node

    // Layer l: out = (A_hat @ X) @ W_l + b_l
    fused_k<<<grid, 256>>>(x,       0, W[0], B[0], nullptr,        1, n); // x    -> g_x
    fused_k<<<grid, 256>>>(nullptr, 1, W[1], B[1], nullptr,        2, n); // g_x  -> g_y
    fused_k<<<grid, 256>>>(nullptr, 2, W[2], B[2], (float*)d_out,  0, n); // g_y  -> d_out
}

// round 3
// speedup vs baseline: 1.5781x; 1.3775x over previous
#include <cuda_runtime.h>

#define NN 100000
#define EE 1600000
#define DD 64

struct __align__(8) Edge { int s; float w; };

// ---- persistent scratch (device globals; no runtime allocation) ----
__device__ int   g_cnt[NN];          // in-degree histogram (edges only)
__device__ int   g_rowptr[NN + 1];   // CSR row pointers (by dst)
__device__ int   g_cursor[NN];       // scatter cursors (init = rowptr)
__device__ float g_dis[NN];          // deg^{-1/2} (deg includes self-loop)
__device__ Edge  g_edge[EE];         // (src, dis[src]*dis[dst]) interleaved
__device__ int   g_bsum[128];        // block sums for 3-phase scan
__device__ float g_x[(size_t)NN * DD];   // activation ping
__device__ float g_y[(size_t)NN * DD];   // activation pong

// ---------------------------------------------------------------------------
__global__ void init_k(int n) {
    int i = blockIdx.x * blockDim.x + threadIdx.x;
    if (i < n) g_cnt[i] = 0;
}

__global__ void hist_k(const int* __restrict__ dst, int e) {
    int i = blockIdx.x * blockDim.x + threadIdx.x;
    if (i < e) atomicAdd(&g_cnt[dst[i]], 1);
}

// Phase 1: per-block (1024) inclusive scan of g_cnt -> g_rowptr[i+1] (local),
// block total -> g_bsum. Also dis = rsqrt(deg+1) for self-loop-added degree.
__global__ void scan1_k(int n) {
    __shared__ int wsum[32];
    const int tid = threadIdx.x, lane = tid & 31, wid = tid >> 5;
    int i = blockIdx.x * 1024 + tid;
    int v = (i < n) ? g_cnt[i] : 0;
    if (i < n) g_dis[i] = rsqrtf((float)(v + 1));
    int x = v;
    #pragma unroll
    for (int o = 1; o < 32; o <<= 1) {
        int y = __shfl_up_sync(0xffffffffu, x, o);
        if (lane >= o) x += y;
    }
    if (lane == 31) wsum[wid] = x;
    __syncthreads();
    if (wid == 0) {
        int s = wsum[lane], t = s;
        #pragma unroll
        for (int o = 1; o < 32; o <<= 1) {
            int y = __shfl_up_sync(0xffffffffu, t, o);
            if (lane >= o) t += y;
        }
        wsum[lane] = t - s;
    }
    __syncthreads();
    int incl = x + wsum[wid];
    if (i < n) g_rowptr[i + 1] = incl;
    if (tid == 1023) g_bsum[blockIdx.x] = incl;
}

// Phase 2: exclusive scan of <=128 block sums.
__global__ void scan2_k(int nb) {
    __shared__ int wsum[4];
    const int tid = threadIdx.x, lane = tid & 31, wid = tid >> 5;
    int v = (tid < nb) ? g_bsum[tid] : 0;
    int x = v;
    #pragma unroll
    for (int o = 1; o < 32; o <<= 1) {
        int y = __shfl_up_sync(0xffffffffu, x, o);
        if (lane >= o) x += y;
    }
    if (lane == 31) wsum[wid] = x;
    __syncthreads();
    int off = 0;
    #pragma unroll
    for (int w = 0; w < 4; w++) if (w < wid) off += wsum[w];
    if (tid < nb) g_bsum[tid] = x - v + off;
}

// Phase 3: finalize rowptr and materialize scatter cursors (= rowptr).
__global__ void scan3_k(int n) {
    int i = blockIdx.x * blockDim.x + threadIdx.x;
    if (i == 0) { g_rowptr[0] = 0; g_cursor[0] = 0; }
    if (i < n) {
        int fin = g_rowptr[i + 1] + g_bsum[i >> 10];
        g_rowptr[i + 1] = fin;
        if (i + 1 < n) g_cursor[i + 1] = fin;
    }
}

__global__ void scat_k(const int* __restrict__ src, const int* __restrict__ dst, int e) {
    int i = blockIdx.x * blockDim.x + threadIdx.x;
    if (i < e) {
        int s = src[i], d = dst[i];
        int pos = atomicAdd(&g_cursor[d], 1);
        Edge ed; ed.s = s; ed.w = g_dis[s] * g_dis[d];
        g_edge[pos] = ed;  // single ST.64: one random line per edge
    }
}

// ---------------------------------------------------------------------------
// Fused GCN layer, 4 nodes per warp:
//   out[n,:] = (dis[n]^2 * X[n,:] + sum_e w[e]*X[src[e],:]) @ W + b
// Lane owns output cols {2l, 2l+1} for all 4 nodes. The mini-GEMM reads each
// W row slice from smem ONCE per 4 nodes (4x less LDS traffic than 1 node/warp).
// Gathers are L2-resident (X = 25.6MB << 126MB L2).
#define NPW 4   // nodes per warp
__global__ void fused_k(const float* __restrict__ Xext, int src_sel,
                        const float* __restrict__ W, const float* __restrict__ bias,
                        float* __restrict__ dout, int dst_sel, int n) {
    __shared__ float Ws[DD * DD];
    for (int i = threadIdx.x; i < DD * DD; i += blockDim.x) Ws[i] = W[i];
    __syncthreads();

    const float* X = (src_sel == 0) ? Xext : (src_sel == 1 ? g_x : g_y);
    float* out     = (dst_sel == 1) ? g_x : (dst_sel == 2 ? g_y : dout);

    const int lane  = threadIdx.x & 31;
    const int warp  = (blockIdx.x * blockDim.x + threadIdx.x) >> 5;
    const int base  = warp * NPW;
    if (base >= n) return;

    float ax[NPW], ay[NPW];

    // ---- aggregate (A_hat @ X rows) for NPW nodes ----
    #pragma unroll
    for (int m = 0; m < NPW; m++) {
        int node = base + m;
        if (node >= n) { ax[m] = 0.f; ay[m] = 0.f; continue; }
        const float dn = g_dis[node];
        float2 hv = reinterpret_cast<const float2*>(X + (size_t)node * DD)[lane];
        const float sw = dn * dn;
        float sx = sw * hv.x, sy = sw * hv.y;

        int j   = g_rowptr[node];
        int end = g_rowptr[node + 1];
        for (; j + 4 <= end; j += 4) {       // 4-wide MLP
            Edge e0 = g_edge[j + 0];
            Edge e1 = g_edge[j + 1];
            Edge e2 = g_edge[j + 2];
            Edge e3 = g_edge[j + 3];
            float2 v0 = reinterpret_cast<const float2*>(X + (size_t)e0.s * DD)[lane];
            float2 v1 = reinterpret_cast<const float2*>(X + (size_t)e1.s * DD)[lane];
            float2 v2 = reinterpret_cast<const float2*>(X + (size_t)e2.s * DD)[lane];
            float2 v3 = reinterpret_cast<const float2*>(X + (size_t)e3.s * DD)[lane];
            sx += e0.w * v0.x; sy += e0.w * v0.y;
            sx += e1.w * v1.x; sy += e1.w * v1.y;
            sx += e2.w * v2.x; sy += e2.w * v2.y;
            sx += e3.w * v3.x; sy += e3.w * v3.y;
        }
        for (; j < end; j++) {
            Edge e = g_edge[j];
            float2 v = reinterpret_cast<const float2*>(X + (size_t)e.s * DD)[lane];
            sx += e.w * v.x; sy += e.w * v.y;
        }
        ax[m] = sx; ay[m] = sy;
    }

    // ---- mini-GEMM: y[m] = agg[m] @ W + b, W slice loaded once per k ----
    float a0[NPW], a1[NPW];
    #pragma unroll
    for (int m = 0; m < NPW; m++) { a0[m] = 0.f; a1[m] = 0.f; }

    #pragma unroll
    for (int k = 0; k < DD; k++) {
        float2 wv = reinterpret_cast<const float2*>(Ws + k * DD)[lane];
        #pragma unroll
        for (int m = 0; m < NPW; m++) {
            float xk = __shfl_sync(0xffffffffu, (k & 1) ? ay[m] : ax[m], k >> 1);
            a0[m] += xk * wv.x;
            a1[m] += xk * wv.y;
        }
    }

    float2 bv = reinterpret_cast<const float2*>(bias)[lane];
    #pragma unroll
    for (int m = 0; m < NPW; m++) {
        int node = base + m;
        if (node >= n) break;
        float2 o; o.x = a0[m] + bv.x; o.y = a1[m] + bv.y;
        reinterpret_cast<float2*>(out + (size_t)node * DD)[lane] = o;
    }
}

// ---------------------------------------------------------------------------
extern "C" void kernel_launch(void* const* d_in, const int* in_sizes, int n_in,
                              void* d_out, int out_size) {
    const float* x  = (const float*)d_in[0];
    const int*   ei = (const int*)d_in[1];
    const float* W[3] = { (const float*)d_in[2], (const float*)d_in[4], (const float*)d_in[6] };
    const float* B[3] = { (const float*)d_in[3], (const float*)d_in[5], (const float*)d_in[7] };

    int n = in_sizes[0] / DD; if (n > NN) n = NN;
    int e = in_sizes[1] / 2;  if (e > EE) e = EE;
    const int* src = ei;
    const int* dst = ei + e;

    // --- build normalized CSR (rebuilt every call; graph fixed across layers) ---
    init_k<<<(n + 255) / 256, 256>>>(n);
    hist_k<<<(e + 255) / 256, 256>>>(dst, e);
    int nb = (n + 1023) / 1024;
    scan1_k<<<nb, 1024>>>(n);
    scan2_k<<<1, 128>>>(nb);
    scan3_k<<<(n + 255) / 256, 256>>>(n);
    scat_k<<<(e + 255) / 256, 256>>>(src, dst, e);

    const int nwarp = (n + NPW - 1) / NPW;
    const int grid  = (nwarp * 32 + 255) / 256;

    // Layer l: out = (A_hat @ X) @ W_l + b_l
    fused_k<<<grid, 256>>>(x,       0, W[0], B[0], nullptr,        1, n); // x    -> g_x
    fused_k<<<grid, 256>>>(nullptr, 1, W[1], B[1], nullptr,        2, n); // g_x  -> g_y
    fused_k<<<grid, 256>>>(nullptr, 2, W[2], B[2], (float*)d_out,  0, n); // g_y  -> d_out
}

// round 4
// speedup vs baseline: 1.6317x; 1.0340x over previous
#include <cuda_runtime.h>

#define NN 100000
#define EE 1600000
#define DD 64

struct __align__(8) Edge { int s; float w; };   // w = dis[src] only

// ---- persistent scratch (device globals; no runtime allocation) ----
__device__ int   g_cnt[NN];          // in-degree histogram (edges only)
__device__ int   g_rowptr[NN + 1];   // CSR row pointers (by dst)
__device__ int   g_cursor[NN];       // scatter cursors (init = rowptr)
__device__ float g_dis[NN];          // deg^{-1/2} (deg includes self-loop)
__device__ Edge  g_edge[EE];         // (src, dis[src]) interleaved
__device__ int   g_bsum[128];        // block sums for scan
__device__ float g_x[(size_t)NN * DD];   // activation ping
__device__ float g_y[(size_t)NN * DD];   // activation pong

// ---------------------------------------------------------------------------
__global__ void hist_k(const int* __restrict__ dst, int e) {
    int i = blockIdx.x * blockDim.x + threadIdx.x;
    if (i < e) atomicAdd(&g_cnt[dst[i]], 1);
}

// Phase 1: per-block (1024) inclusive scan of g_cnt -> g_rowptr[i+1] (local),
// block total -> g_bsum. Also dis = rsqrt(deg+1) for self-loop-added degree.
__global__ void scan1_k(int n) {
    __shared__ int wsum[32];
    const int tid = threadIdx.x, lane = tid & 31, wid = tid >> 5;
    int i = blockIdx.x * 1024 + tid;
    int v = (i < n) ? g_cnt[i] : 0;
    if (i < n) g_dis[i] = rsqrtf((float)(v + 1));
    int x = v;
    #pragma unroll
    for (int o = 1; o < 32; o <<= 1) {
        int y = __shfl_up_sync(0xffffffffu, x, o);
        if (lane >= o) x += y;
    }
    if (lane == 31) wsum[wid] = x;
    __syncthreads();
    if (wid == 0) {
        int s = wsum[lane], t = s;
        #pragma unroll
        for (int o = 1; o < 32; o <<= 1) {
            int y = __shfl_up_sync(0xffffffffu, t, o);
            if (lane >= o) t += y;
        }
        wsum[lane] = t - s;
    }
    __syncthreads();
    int incl = x + wsum[wid];
    if (i < n) g_rowptr[i + 1] = incl;
    if (tid == 1023) g_bsum[blockIdx.x] = incl;
}

// Phase 2+3 fused: every block recomputes the exclusive prefix of the <=128
// block sums in smem (cheap, broadcast loads), then finalizes rowptr and
// materializes scatter cursors (= rowptr).
__global__ void scan3_k(int n, int nb) {
    __shared__ int pref[128];
    __shared__ int wsum[4];
    const int tid = threadIdx.x, lane = tid & 31, wid = tid >> 5;

    int v = 0, x = 0;
    if (tid < 128) {
        v = (tid < nb) ? g_bsum[tid] : 0;
        x = v;
        #pragma unroll
        for (int o = 1; o < 32; o <<= 1) {
            int y = __shfl_up_sync(0xffffffffu, x, o);
            if (lane >= o) x += y;
        }
        if (lane == 31) wsum[wid] = x;
    }
    __syncthreads();
    if (tid < 128) {
        int off = 0;
        #pragma unroll
        for (int w = 0; w < 4; w++) if (w < wid) off += wsum[w];
        pref[tid] = x - v + off;    // exclusive prefix of block sums
    }
    __syncthreads();

    int i = blockIdx.x * blockDim.x + tid;
    if (i == 0) { g_rowptr[0] = 0; g_cursor[0] = 0; }
    if (i < n) {
        int fin = g_rowptr[i + 1] + pref[i >> 10];
        g_rowptr[i + 1] = fin;
        if (i + 1 < n) g_cursor[i + 1] = fin;
    }
}

__global__ void scat_k(const int* __restrict__ src, const int* __restrict__ dst, int e) {
    int i = blockIdx.x * blockDim.x + threadIdx.x;
    if (i < e) {
        int s = src[i], d = dst[i];
        int pos = atomicAdd(&g_cursor[d], 1);
        Edge ed; ed.s = s; ed.w = g_dis[s];   // dis[dst] folded into fused epilogue
        g_edge[pos] = ed;                     // single ST.64: one random sector/edge
    }
}

// ---------------------------------------------------------------------------
// Fused GCN layer, 4 nodes per warp, normalization factored:
//   out[n,:] = ( dn * (dn*X[n,:] + sum_e dis[src_e]*X[src_e,:]) ) @ W + b
// Lane owns output cols {2l, 2l+1} for all 4 nodes; W row slice read from
// smem once per 4 nodes. Gathers are L2-resident (X = 25.6MB << 126MB L2).
#define NPW 4
__global__ void fused_k(const float* __restrict__ Xext, int src_sel,
                        const float* __restrict__ W, const float* __restrict__ bias,
                        float* __restrict__ dout, int dst_sel, int n) {
    __shared__ float Ws[DD * DD];
    for (int i = threadIdx.x; i < DD * DD; i += blockDim.x) Ws[i] = W[i];
    __syncthreads();

    const float* X = (src_sel == 0) ? Xext : (src_sel == 1 ? g_x : g_y);
    float* out     = (dst_sel == 1) ? g_x : (dst_sel == 2 ? g_y : dout);

    const int lane = threadIdx.x & 31;
    const int warp = (blockIdx.x * blockDim.x + threadIdx.x) >> 5;
    const int base = warp * NPW;
    if (base >= n) return;

    float ax[NPW], ay[NPW];

    #pragma unroll
    for (int m = 0; m < NPW; m++) {
        int node = base + m;
        if (node >= n) { ax[m] = 0.f; ay[m] = 0.f; continue; }
        const float dn = g_dis[node];
        float2 hv = reinterpret_cast<const float2*>(X + (size_t)node * DD)[lane];
        float sx = dn * hv.x, sy = dn * hv.y;    // self term (pre dn-scale)

        int j   = g_rowptr[node];
        int end = g_rowptr[node + 1];
        for (; j + 4 <= end; j += 4) {           // 4 gathers in flight
            Edge e0 = g_edge[j + 0];
            Edge e1 = g_edge[j + 1];
            Edge e2 = g_edge[j + 2];
            Edge e3 = g_edge[j + 3];
            float2 v0 = reinterpret_cast<const float2*>(X + (size_t)e0.s * DD)[lane];
            float2 v1 = reinterpret_cast<const float2*>(X + (size_t)e1.s * DD)[lane];
            float2 v2 = reinterpret_cast<const float2*>(X + (size_t)e2.s * DD)[lane];
            float2 v3 = reinterpret_cast<const float2*>(X + (size_t)e3.s * DD)[lane];
            sx += e0.w * v0.x; sy += e0.w * v0.y;
            sx += e1.w * v1.x; sy += e1.w * v1.y;
            sx += e2.w * v2.x; sy += e2.w * v2.y;
            sx += e3.w * v3.x; sy += e3.w * v3.y;
        }
        for (; j < end; j++) {
            Edge e = g_edge[j];
            float2 v = reinterpret_cast<const float2*>(X + (size_t)e.s * DD)[lane];
            sx += e.w * v.x; sy += e.w * v.y;
        }
        ax[m] = dn * sx;                          // dis[dst] applied once
        ay[m] = dn * sy;
    }

    // ---- mini-GEMM: y[m] = agg[m] @ W + b ----
    float a0[NPW], a1[NPW];
    #pragma unroll
    for (int m = 0; m < NPW; m++) { a0[m] = 0.f; a1[m] = 0.f; }

    #pragma unroll
    for (int k = 0; k < DD; k++) {
        float2 wv = reinterpret_cast<const float2*>(Ws + k * DD)[lane];
        #pragma unroll
        for (int m = 0; m < NPW; m++) {
            float xk = __shfl_sync(0xffffffffu, (k & 1) ? ay[m] : ax[m], k >> 1);
            a0[m] += xk * wv.x;
            a1[m] += xk * wv.y;
        }
    }

    float2 bv = reinterpret_cast<const float2*>(bias)[lane];
    #pragma unroll
    for (int m = 0; m < NPW; m++) {
        int node = base + m;
        if (node >= n) break;
        float2 o; o.x = a0[m] + bv.x; o.y = a1[m] + bv.y;
        reinterpret_cast<float2*>(out + (size_t)node * DD)[lane] = o;
    }
}

// ---------------------------------------------------------------------------
extern "C" void kernel_launch(void* const* d_in, const int* in_sizes, int n_in,
                              void* d_out, int out_size) {
    const float* x  = (const float*)d_in[0];
    const int*   ei = (const int*)d_in[1];
    const float* W[3] = { (const float*)d_in[2], (const float*)d_in[4], (const float*)d_in[6] };
    const float* B[3] = { (const float*)d_in[3], (const float*)d_in[5], (const float*)d_in[7] };

    int n = in_sizes[0] / DD; if (n > NN) n = NN;
    int e = in_sizes[1] / 2;  if (e > EE) e = EE;
    const int* src = ei;
    const int* dst = ei + e;

    // --- build normalized CSR (rebuilt every call; graph fixed across layers) ---
    void* cnt_ptr = nullptr;
    cudaGetSymbolAddress(&cnt_ptr, g_cnt);
    cudaMemsetAsync(cnt_ptr, 0, (size_t)n * sizeof(int));

    hist_k<<<(e + 255) / 256, 256>>>(dst, e);
    int nb = (n + 1023) / 1024;
    scan1_k<<<nb, 1024>>>(n);
    scan3_k<<<(n + 255) / 256, 256>>>(n, nb);
    scat_k<<<(e + 255) / 256, 256>>>(src, dst, e);

    const int nwarp = (n + NPW - 1) / NPW;
    const int grid  = (nwarp * 32 + 255) / 256;

    // Layer l: out = (A_hat @ X) @ W_l + b_l
    fused_k<<<grid, 256>>>(x,       0, W[0], B[0], nullptr,        1, n); // x    -> g_x
    fused_k<<<grid, 256>>>(nullptr, 1, W[1], B[1], nullptr,        2, n); // g_x  -> g_y
    fused_k<<<grid, 256>>>(nullptr, 2, W[2], B[2], (float*)d_out,  0, n); // g_y  -> d_out
}

// round 6
// speedup vs baseline: 1.7468x; 1.0705x over previous
#include <cuda_runtime.h>
#include <cuda_fp16.h>

#define NN 100000
#define EE 1600000
#define DD 64

// ---- persistent scratch (device globals; no runtime allocation) ----
__device__ int    g_cnt[NN];          // in-degree histogram (edges only)
__device__ int    g_rowptr[NN + 1];   // CSR row pointers (by dst)
__device__ int    g_cursor[NN];       // scatter cursors (init = rowptr)
__device__ float  g_dis[NN];          // deg^{-1/2} (deg includes self-loop)
__device__ int    g_col[EE];          // CSR column = src node (weight folded into X')
__device__ int    g_bsum[128];        // block sums for scan
__device__ __half g_hx[(size_t)NN * DD];  // pre-scaled fp16 activation ping
__device__ __half g_hy[(size_t)NN * DD];  // pre-scaled fp16 activation pong

// ---------------------------------------------------------------------------
__global__ void hist_k(const int* __restrict__ dst, int e) {
    int i = blockIdx.x * blockDim.x + threadIdx.x;
    if (i < e) atomicAdd(&g_cnt[dst[i]], 1);
}

// Phase 1: per-block (1024) inclusive scan of g_cnt -> g_rowptr[i+1] (local),
// block total -> g_bsum. Also dis = rsqrt(deg+1) for self-loop-added degree.
__global__ void scan1_k(int n) {
    __shared__ int wsum[32];
    const int tid = threadIdx.x, lane = tid & 31, wid = tid >> 5;
    int i = blockIdx.x * 1024 + tid;
    int v = (i < n) ? g_cnt[i] : 0;
    if (i < n) g_dis[i] = rsqrtf((float)(v + 1));
    int x = v;
    #pragma unroll
    for (int o = 1; o < 32; o <<= 1) {
        int y = __shfl_up_sync(0xffffffffu, x, o);
        if (lane >= o) x += y;
    }
    if (lane == 31) wsum[wid] = x;
    __syncthreads();
    if (wid == 0) {
        int s = wsum[lane], t = s;
        #pragma unroll
        for (int o = 1; o < 32; o <<= 1) {
            int y = __shfl_up_sync(0xffffffffu, t, o);
            if (lane >= o) t += y;
        }
        wsum[lane] = t - s;
    }
    __syncthreads();
    int incl = x + wsum[wid];
    if (i < n) g_rowptr[i + 1] = incl;
    if (tid == 1023) g_bsum[blockIdx.x] = incl;
}

// Phase 2+3 fused: every block recomputes the exclusive prefix of the <=128
// block sums in smem, then finalizes rowptr and materializes scatter cursors.
__global__ void scan3_k(int n, int nb) {
    __shared__ int pref[128];
    __shared__ int wsum[4];
    const int tid = threadIdx.x, lane = tid & 31, wid = tid >> 5;

    int v = 0, x = 0;
    if (tid < 128) {
        v = (tid < nb) ? g_bsum[tid] : 0;
        x = v;
        #pragma unroll
        for (int o = 1; o < 32; o <<= 1) {
            int y = __shfl_up_sync(0xffffffffu, x, o);
            if (lane >= o) x += y;
        }
        if (lane == 31) wsum[wid] = x;
    }
    __syncthreads();
    if (tid < 128) {
        int off = 0;
        #pragma unroll
        for (int w = 0; w < 4; w++) if (w < wid) off += wsum[w];
        pref[tid] = x - v + off;
    }
    __syncthreads();

    int i = blockIdx.x * blockDim.x + tid;
    if (i == 0) { g_rowptr[0] = 0; g_cursor[0] = 0; }
    if (i < n) {
        int fin = g_rowptr[i + 1] + pref[i >> 10];
        g_rowptr[i + 1] = fin;
        if (i + 1 < n) g_cursor[i + 1] = fin;
    }
}

// Scatter: bare src index only (4B random store; dis folded into activations).
__global__ void scat_k(const int* __restrict__ src, const int* __restrict__ dst, int e) {
    int i = blockIdx.x * blockDim.x + threadIdx.x;
    if (i < e) {
        int d = dst[i];
        int pos = atomicAdd(&g_cursor[d], 1);
        g_col[pos] = src[i];
    }
}

// Layer-0 prep: g_hx[n,c] = half( dis[n] * x[n,c] )  (pre-scaled activations)
__global__ void prescale_k(const float* __restrict__ x, int n2) {
    int i = blockIdx.x * blockDim.x + threadIdx.x;   // i indexes half2 pairs
    if (i >= n2) return;
    float d = g_dis[i >> 5];                          // 32 half2 per row
    float2 v = reinterpret_cast<const float2*>(x)[i];
    v.x *= d; v.y *= d;
    reinterpret_cast<__half2*>(g_hx)[i] = __float22half2_rn(v);
}

// ---------------------------------------------------------------------------
// Fused GCN layer on pre-scaled fp16 activations (X' = dis.*X), 4 nodes/warp:
//   S[n]   = X'[n] + sum_e X'[src_e]        <- self term is BARE X'[n]
//   out[n] = (dn * S[n]) @ W + b            (fp32 mini-GEMM; dn*X'[n]=dn^2 X[n])
//   next X'[n] = half( dn * out[n] )  or fp32 out to d_out (last layer)
#define NPW 4
__global__ void fused_k(int src_sel, const float* __restrict__ W,
                        const float* __restrict__ bias,
                        float* __restrict__ dout, int last, int n) {
    __shared__ float Ws[DD * DD];
    for (int i = threadIdx.x; i < DD * DD; i += blockDim.x) Ws[i] = W[i];
    __syncthreads();

    const __half* X = src_sel ? g_hy : g_hx;
    __half* Xo      = src_sel ? g_hx : g_hy;

    const int lane = threadIdx.x & 31;
    const int warp = (blockIdx.x * blockDim.x + threadIdx.x) >> 5;
    const int base = warp * NPW;
    if (base >= n) return;

    float ax[NPW], ay[NPW], dnr[NPW];

    #pragma unroll
    for (int m = 0; m < NPW; m++) {
        int node = base + m;
        if (node >= n) { ax[m] = 0.f; ay[m] = 0.f; dnr[m] = 0.f; continue; }
        const float dn = g_dis[node];
        dnr[m] = dn;
        float2 hv = __half22float2(
            reinterpret_cast<const __half2*>(X + (size_t)node * DD)[lane]);
        float sx = hv.x, sy = hv.y;             // self term: bare X'[n]

        int j   = g_rowptr[node];
        int end = g_rowptr[node + 1];
        for (; j + 4 <= end; j += 4) {          // 4 gathers in flight
            int s0 = g_col[j + 0];
            int s1 = g_col[j + 1];
            int s2 = g_col[j + 2];
            int s3 = g_col[j + 3];
            float2 v0 = __half22float2(reinterpret_cast<const __half2*>(X + (size_t)s0 * DD)[lane]);
            float2 v1 = __half22float2(reinterpret_cast<const __half2*>(X + (size_t)s1 * DD)[lane]);
            float2 v2 = __half22float2(reinterpret_cast<const __half2*>(X + (size_t)s2 * DD)[lane]);
            float2 v3 = __half22float2(reinterpret_cast<const __half2*>(X + (size_t)s3 * DD)[lane]);
            sx += v0.x; sy += v0.y;
            sx += v1.x; sy += v1.y;
            sx += v2.x; sy += v2.y;
            sx += v3.x; sy += v3.y;
        }
        for (; j < end; j++) {
            int s = g_col[j];
            float2 v = __half22float2(reinterpret_cast<const __half2*>(X + (size_t)s * DD)[lane]);
            sx += v.x; sy += v.y;
        }
        ax[m] = dn * sx;                        // Â X[n] = dn * S[n]
        ay[m] = dn * sy;
    }

    // ---- mini-GEMM: y[m] = agg[m] @ W + b, W slice read once per 4 nodes ----
    float a0[NPW], a1[NPW];
    #pragma unroll
    for (int m = 0; m < NPW; m++) { a0[m] = 0.f; a1[m] = 0.f; }

    #pragma unroll
    for (int k = 0; k < DD; k++) {
        float2 wv = reinterpret_cast<const float2*>(Ws + k * DD)[lane];
        #pragma unroll
        for (int m = 0; m < NPW; m++) {
            float xk = __shfl_sync(0xffffffffu, (k & 1) ? ay[m] : ax[m], k >> 1);
            a0[m] += xk * wv.x;
            a1[m] += xk * wv.y;
        }
    }

    float2 bv = reinterpret_cast<const float2*>(bias)[lane];
    #pragma unroll
    for (int m = 0; m < NPW; m++) {
        int node = base + m;
        if (node >= n) break;
        float ox = a0[m] + bv.x, oy = a1[m] + bv.y;
        if (last) {
            float2 o; o.x = ox; o.y = oy;
            reinterpret_cast<float2*>(dout + (size_t)node * DD)[lane] = o;
        } else {
            float d = dnr[m];                   // pre-scale for next layer
            float2 o; o.x = d * ox; o.y = d * oy;
            reinterpret_cast<__half2*>(Xo + (size_t)node * DD)[lane] = __float22half2_rn(o);
        }
    }
}

// ---------------------------------------------------------------------------
extern "C" void kernel_launch(void* const* d_in, const int* in_sizes, int n_in,
                              void* d_out, int out_size) {
    const float* x  = (const float*)d_in[0];
    const int*   ei = (const int*)d_in[1];
    const float* W[3] = { (const float*)d_in[2], (const float*)d_in[4], (const float*)d_in[6] };
    const float* B[3] = { (const float*)d_in[3], (const float*)d_in[5], (const float*)d_in[7] };

    int n = in_sizes[0] / DD; if (n > NN) n = NN;
    int e = in_sizes[1] / 2;  if (e > EE) e = EE;
    const int* src = ei;
    const int* dst = ei + e;

    // --- build CSR (rebuilt every call; graph fixed across layers) ---
    void* cnt_ptr = nullptr;
    cudaGetSymbolAddress(&cnt_ptr, g_cnt);
    cudaMemsetAsync(cnt_ptr, 0, (size_t)n * sizeof(int));

    hist_k<<<(e + 255) / 256, 256>>>(dst, e);
    int nb = (n + 1023) / 1024;
    scan1_k<<<nb, 1024>>>(n);
    scan3_k<<<(n + 255) / 256, 256>>>(n, nb);
    prescale_k<<<(n * (DD / 2) + 255) / 256, 256>>>(x, n * (DD / 2));
    scat_k<<<(e + 255) / 256, 256>>>(src, dst, e);

    const int nwarp = (n + NPW - 1) / NPW;
    const int grid  = (nwarp * 32 + 255) / 256;

    fused_k<<<grid, 256>>>(0, W[0], B[0], nullptr,       0, n); // g_hx -> g_hy
    fused_k<<<grid, 256>>>(1, W[1], B[1], nullptr,       0, n); // g_hy -> g_hx
    fused_k<<<grid, 256>>>(0, W[2], B[2], (float*)d_out, 1, n); // g_hx -> d_out
}